// round 16
// baseline (speedup 1.0000x reference)
#include <cuda_runtime.h>
#include <cuda_bf16.h>
#include <math.h>

#define S_SAMPLES 384
#define MAXN 4096
#define VOXD 128
#define CHANS 27
#define CH_STRIDE (128*128*128)

__device__ float g_alpha[MAXN * S_SAMPLES];
__device__ float g_weight[MAXN * S_SAMPLES];

// ---- packed f32x2 helpers (FFMA2 via PTX; legal on sm_100 target) ----
#define FFMA2(acc, a, b) \
    asm("fma.rn.f32x2 %0, %1, %2, %0;" : "+l"(acc) : "l"(a), "l"(b))
#define DUPF(dst, fu) \
    asm("mov.b64 %0, {%1, %1};" : "=l"(dst) : "r"(fu))
#define UNPK(lo, hi, v) \
    asm("mov.b64 {%0, %1}, %2;" : "=r"(lo), "=r"(hi) : "l"(v))
#define PACK_BF16X2(out, lo, hi) \
    asm("cvt.rn.bf16x2.f32 %0, %1, %2;" : "=r"(out) : "f"(hi), "f"(lo))

__device__ __forceinline__ float softplus_shift(float v) {
    float x = v - 10.0f;
    return (x > 20.0f) ? x : log1pf(expf(x));
}

struct Tri { int o[8]; float w[8]; };

__device__ __forceinline__ Tri make_tri(float px, float py, float pz) {
    const float k = 2.0f / 3.0f;
    float cx = fminf(fmaxf((px + 1.5f) * k - 1.0f, -1.0f), 1.0f);
    float cy = fminf(fmaxf((py + 1.5f) * k - 1.0f, -1.0f), 1.0f);
    float cz = fminf(fmaxf((pz + 1.5f) * k - 1.0f, -1.0f), 1.0f);
    float fx = (cx + 1.0f) * 63.5f;
    float fy = (cy + 1.0f) * 63.5f;
    float fz = (cz + 1.0f) * 63.5f;
    float x0f = floorf(fx), y0f = floorf(fy), z0f = floorf(fz);
    float wx = fx - x0f, wy = fy - y0f, wz = fz - z0f;
    int ix0 = min(max((int)x0f, 0), 127); int ix1 = min(ix0 + 1, 127);
    int iy0 = min(max((int)y0f, 0), 127); int iy1 = min(iy0 + 1, 127);
    int iz0 = min(max((int)z0f, 0), 127); int iz1 = min(iz0 + 1, 127);
    Tri t;
    int b00 = (iz0 * VOXD + iy0) * VOXD;
    int b01 = (iz0 * VOXD + iy1) * VOXD;
    int b10 = (iz1 * VOXD + iy0) * VOXD;
    int b11 = (iz1 * VOXD + iy1) * VOXD;
    t.o[0] = b00 + ix0; t.o[1] = b00 + ix1;
    t.o[2] = b01 + ix0; t.o[3] = b01 + ix1;
    t.o[4] = b10 + ix0; t.o[5] = b10 + ix1;
    t.o[6] = b11 + ix0; t.o[7] = b11 + ix1;
    float ux = 1.0f - wx, uy = 1.0f - wy, uz = 1.0f - wz;
    t.w[0] = ux * uy * uz; t.w[1] = wx * uy * uz;
    t.w[2] = ux * wy * uz; t.w[3] = wx * wy * uz;
    t.w[4] = ux * uy * wz; t.w[5] = wx * uy * wz;
    t.w[6] = ux * wy * wz; t.w[7] = wx * wy * wz;
    return t;
}

// ---------------- kernel 1: per-sample alpha ----------------
__global__ void sigma_kernel(const float* __restrict__ rays_o,
                             const float* __restrict__ rays_d,
                             const float* __restrict__ dvol, int N) {
    int idx = blockIdx.x * blockDim.x + threadIdx.x;
    if (idx >= N * S_SAMPLES) return;
    int r = idx / S_SAMPLES;
    int s = idx - r * S_SAMPLES;
    float z = 2.0f + (4.0f / 383.0f) * (float)s;
    float px = rays_o[3*r+0] + rays_d[3*r+0] * z;
    float py = rays_o[3*r+1] + rays_d[3*r+1] * z;
    float pz = rays_o[3*r+2] + rays_d[3*r+2] * z;
    bool inb = (px >= -1.5f && px <= 1.5f && py >= -1.5f && py <= 1.5f &&
                pz >= -1.5f && pz <= 1.5f);
    float alpha = 0.0f;
    if (inb && s < S_SAMPLES - 1) {
        Tri t = make_tri(px, py, pz);
        float feat = 0.0f;
        #pragma unroll
        for (int c = 0; c < 8; c++) feat += __ldg(&dvol[t.o[c]]) * t.w[c];
        float sigma = softplus_shift(feat);
        float dist = (2.0f + (4.0f/383.0f)*(float)(s+1)) - z;
        alpha = 1.0f - expf(-sigma * dist * 25.0f);
    }
    g_alpha[idx] = alpha;
}

// ---------------- kernel 2: per-ray transmittance scan ----------------
__global__ void scan_kernel(float* __restrict__ out, int N) {
    int r = blockIdx.x * blockDim.x + threadIdx.x;
    if (r >= N) return;
    float T = 1.0f, acc = 0.0f;
    const int base = r * S_SAMPLES;
    for (int s = 0; s < S_SAMPLES; s++) {
        float a = g_alpha[base + s];
        float w = a * T;
        g_weight[base + s] = w;
        acc += w;
        T *= (1.0f - a + 1e-10f);
    }
    float bg = 1.0f - acc;
    out[3*r+0] = bg; out[3*r+1] = bg; out[3*r+2] = bg;
}

// ---------------- kernel 3: features + MLP + composite ----------------
// smem: weights only (x/h live in true registers via full unroll)
#define OFF_W1   0          // 13056
#define OFF_W2   13056      // 16384
#define OFF_W3   29440      // 384
#define OFF_B1   29824      // 128
#define OFF_B2   29952      // 128
#define OFF_B3   30080      // 4
#define OFF_ACC  30084      // 8 (2 rays x 3ch)
#define SMEM_FLOATS 30092
#define SMEM_BYTES  (SMEM_FLOATS * 4)   // 120368

#define MLP_THREADS 256

__global__ void __launch_bounds__(MLP_THREADS, 1)
mlp_kernel(const float* __restrict__ rays_o,
           const float* __restrict__ rays_d,
           const float* __restrict__ avol,
           const float* __restrict__ W1, const float* __restrict__ b1,
           const float* __restrict__ W2, const float* __restrict__ b2,
           const float* __restrict__ W3, const float* __restrict__ b3,
           float* __restrict__ out, int N, int blk_ofs) {
    extern __shared__ float sm[];
    const int tid = threadIdx.x;
    const int blk = blockIdx.x + blk_ofs;
    const int g = blk * MLP_THREADS + tid;
    const int r = g / S_SAMPLES;
    const int s = g - r * S_SAMPLES;
    const int r0 = (blk * MLP_THREADS) / S_SAMPLES;

    float w = g_weight[g];
    bool active = (w > 0.0f);
    if (!__syncthreads_or(active)) return;   // whole block dead -> skip

    // stage weights into shared
    {
        const float4* g1 = (const float4*)W1;
        float4* s1 = (float4*)&sm[OFF_W1];
        for (int i = tid; i < 13056/4; i += MLP_THREADS) s1[i] = g1[i];
        const float4* g2 = (const float4*)W2;
        float4* s2 = (float4*)&sm[OFF_W2];
        for (int i = tid; i < 16384/4; i += MLP_THREADS) s2[i] = g2[i];
        if (tid < 128) { sm[OFF_B1 + tid] = b1[tid]; sm[OFF_B2 + tid] = b2[tid]; }
        for (int i = tid; i < 384; i += MLP_THREADS) sm[OFF_W3 + i] = W3[i];
        if (tid < 3) sm[OFF_B3 + tid] = b3[tid];
        if (tid < 8) sm[OFF_ACC + tid] = 0.0f;
    }
    __syncthreads();

    if (active) {
        // ---- features -> xp[51] bf16x2 in TRUE registers ----
        unsigned int xp[51];
        {
            float z = 2.0f + (4.0f / 383.0f) * (float)s;
            float dx = rays_d[3*r+0], dy = rays_d[3*r+1], dz = rays_d[3*r+2];
            float px = rays_o[3*r+0] + dx * z;
            float py = rays_o[3*r+1] + dy * z;
            float pz = rays_o[3*r+2] + dz * z;

            float feat[30];
            Tri t = make_tri(px, py, pz);
            #pragma unroll
            for (int c = 0; c < CHANS; c++) {
                const float* v = avol + (size_t)c * CH_STRIDE;
                float acc = 0.0f;
                #pragma unroll
                for (int k = 0; k < 8; k++) acc += __ldg(&v[t.o[k]]) * t.w[k];
                feat[c] = acc;
            }
            feat[27] = dx; feat[28] = dy; feat[29] = dz;
            #pragma unroll
            for (int p = 0; p < 15; p++)
                PACK_BF16X2(xp[p], feat[2*p], feat[2*p+1]);
            // PE pairs: sin(pts) 15..23, cos(pts) 24..32,
            //           sin(view) 33..41, cos(view) 42..50
            float p3[3] = {px, py, pz};
            #pragma unroll
            for (int ci = 0; ci < 3; ci++)
                #pragma unroll
                for (int q2 = 0; q2 < 3; q2++) {
                    float a0 = p3[ci] * (float)(1 << (2*q2));
                    float a1 = p3[ci] * (float)(1 << (2*q2+1));
                    float s0, c0, s1, c1;
                    sincosf(a0, &s0, &c0);
                    sincosf(a1, &s1, &c1);
                    PACK_BF16X2(xp[15 + ci*3 + q2], s0, s1);
                    PACK_BF16X2(xp[24 + ci*3 + q2], c0, c1);
                }
            float d3[3] = {dx, dy, dz};
            #pragma unroll
            for (int ci = 0; ci < 3; ci++)
                #pragma unroll
                for (int q2 = 0; q2 < 3; q2++) {
                    float a0 = d3[ci] * (float)(1 << (2*q2));
                    float a1 = d3[ci] * (float)(1 << (2*q2+1));
                    float s0, c0, s1, c1;
                    sincosf(a0, &s0, &c0);
                    sincosf(a1, &s1, &c1);
                    PACK_BF16X2(xp[33 + ci*3 + q2], s0, s1);
                    PACK_BF16X2(xp[42 + ci*3 + q2], c0, c1);
                }
        }

        // ---- layer 1: k-outer, FULLY UNROLLED (xp stays in registers) ----
        unsigned long long acc1[64];
        {
            const unsigned long long* bp =
                (const unsigned long long*)&sm[OFF_B1];
            #pragma unroll
            for (int j = 0; j < 64; j++) acc1[j] = bp[j];
        }
        #pragma unroll
        for (int kp = 0; kp < 51; kp++) {
            unsigned int hp = xp[kp];
            unsigned long long xx0, xx1;
            DUPF(xx0, hp << 16);                 // x[2kp]
            DUPF(xx1, hp & 0xffff0000u);         // x[2kp+1]
            const ulonglong2* w0 =
                (const ulonglong2*)&sm[OFF_W1 + (2*kp) * 128];
            const ulonglong2* w1 =
                (const ulonglong2*)&sm[OFF_W1 + (2*kp+1) * 128];
            #pragma unroll
            for (int j = 0; j < 32; j++) {
                ulonglong2 ww = w0[j];
                FFMA2(acc1[2*j],   xx0, ww.x);
                FFMA2(acc1[2*j+1], xx0, ww.y);
            }
            #pragma unroll
            for (int j = 0; j < 32; j++) {
                ulonglong2 ww = w1[j];
                FFMA2(acc1[2*j],   xx1, ww.x);
                FFMA2(acc1[2*j+1], xx1, ww.y);
            }
        }
        // relu + pack h1 into 64 TRUE registers (acc1, xp die here)
        unsigned int h[64];
        #pragma unroll
        for (int j = 0; j < 64; j++) {
            unsigned int lo, hi;
            UNPK(lo, hi, acc1[j]);
            float a0 = fmaxf(__uint_as_float(lo), 0.0f);
            float a1 = fmaxf(__uint_as_float(hi), 0.0f);
            PACK_BF16X2(h[j], a0, a1);
        }

        // ---- layer 2: k-outer, FULLY UNROLLED (h stays in registers) ----
        unsigned long long acc2[64];
        {
            const unsigned long long* bp =
                (const unsigned long long*)&sm[OFF_B2];
            #pragma unroll
            for (int j = 0; j < 64; j++) acc2[j] = bp[j];
        }
        #pragma unroll
        for (int kp = 0; kp < 64; kp++) {
            unsigned int hp = h[kp];
            unsigned long long xx0, xx1;
            DUPF(xx0, hp << 16);
            DUPF(xx1, hp & 0xffff0000u);
            const ulonglong2* w0 =
                (const ulonglong2*)&sm[OFF_W2 + (2*kp) * 128];
            const ulonglong2* w1 =
                (const ulonglong2*)&sm[OFF_W2 + (2*kp+1) * 128];
            #pragma unroll
            for (int j = 0; j < 32; j++) {
                ulonglong2 ww = w0[j];
                FFMA2(acc2[2*j],   xx0, ww.x);
                FFMA2(acc2[2*j+1], xx0, ww.y);
            }
            #pragma unroll
            for (int j = 0; j < 32; j++) {
                ulonglong2 ww = w1[j];
                FFMA2(acc2[2*j],   xx1, ww.x);
                FFMA2(acc2[2*j+1], xx1, ww.y);
            }
        }

        // ---- layer 3 epilogue: relu(h2), 128->3, sigmoid, composite ----
        float o0 = sm[OFF_B3 + 0], o1 = sm[OFF_B3 + 1], o2 = sm[OFF_B3 + 2];
        #pragma unroll
        for (int j = 0; j < 64; j++) {
            unsigned int lo, hi;
            UNPK(lo, hi, acc2[j]);
            float a0 = fmaxf(__uint_as_float(lo), 0.0f);
            float a1 = fmaxf(__uint_as_float(hi), 0.0f);
            int col = 2*j;
            o0 = fmaf(a0, sm[OFF_W3 + col*3 + 0], o0);
            o1 = fmaf(a0, sm[OFF_W3 + col*3 + 1], o1);
            o2 = fmaf(a0, sm[OFF_W3 + col*3 + 2], o2);
            o0 = fmaf(a1, sm[OFF_W3 + (col+1)*3 + 0], o0);
            o1 = fmaf(a1, sm[OFF_W3 + (col+1)*3 + 1], o1);
            o2 = fmaf(a1, sm[OFF_W3 + (col+1)*3 + 2], o2);
        }
        float r0v = 1.0f / (1.0f + __expf(-o0));
        float r1v = 1.0f / (1.0f + __expf(-o1));
        float r2v = 1.0f / (1.0f + __expf(-o2));
        int li = r - r0;
        atomicAdd(&sm[OFF_ACC + li*3 + 0], w * r0v);
        atomicAdd(&sm[OFF_ACC + li*3 + 1], w * r1v);
        atomicAdd(&sm[OFF_ACC + li*3 + 2], w * r2v);
    }
    __syncthreads();
    if (tid < 6) {
        int li = tid / 3, c = tid - li * 3;
        int ray = r0 + li;
        if (ray < N) atomicAdd(&out[3*ray + c], sm[OFF_ACC + tid]);
    }
}

// ---------------- kernel 4: clamp ----------------
__global__ void clamp_kernel(float* __restrict__ out, int n) {
    int i = blockIdx.x * blockDim.x + threadIdx.x;
    if (i < n) out[i] = fminf(fmaxf(out[i], 0.0f), 1.0f);
}

extern "C" void kernel_launch(void* const* d_in, const int* in_sizes, int n_in,
                              void* d_out, int out_size) {
    const float* rays_o = (const float*)d_in[0];
    const float* rays_d = (const float*)d_in[1];
    const float* dvol   = (const float*)d_in[2];
    const float* avol   = (const float*)d_in[3];
    const float* W1     = (const float*)d_in[4];
    const float* b1     = (const float*)d_in[5];
    const float* W2     = (const float*)d_in[6];
    const float* b2     = (const float*)d_in[7];
    const float* W3     = (const float*)d_in[8];
    const float* b3     = (const float*)d_in[9];
    float* out = (float*)d_out;
    int N = in_sizes[0] / 3;
    if (N > MAXN) N = MAXN;

    cudaFuncSetAttribute(mlp_kernel,
                         cudaFuncAttributeMaxDynamicSharedMemorySize, SMEM_BYTES);

    int total = N * S_SAMPLES;
    sigma_kernel<<<(total + 255) / 256, 256>>>(rays_o, rays_d, dvol, N);
    scan_kernel<<<(N + 255) / 256, 256>>>(out, N);
    int blocks = (total + MLP_THREADS - 1) / MLP_THREADS;
    int half = blocks / 2;
    mlp_kernel<<<half, MLP_THREADS, SMEM_BYTES>>>(rays_o, rays_d, avol,
                                    W1, b1, W2, b2, W3, b3, out, N, 0);
    mlp_kernel<<<blocks - half, MLP_THREADS, SMEM_BYTES>>>(rays_o, rays_d, avol,
                                    W1, b1, W2, b2, W3, b3, out, N, half);
    clamp_kernel<<<(N * 3 + 255) / 256, 256>>>(out, N * 3);
}

// round 17
// speedup vs baseline: 1.9390x; 1.9390x over previous
#include <cuda_runtime.h>
#include <cuda_bf16.h>
#include <math.h>

#define S_SAMPLES 384
#define MAXN 4096
#define VOXD 128
#define CHANS 27
#define CH_STRIDE (128*128*128)
#define TOTS (MAXN * S_SAMPLES)      // h1 stride (compile-time)

__device__ float g_alpha[TOTS];
__device__ float g_weight[TOTS];
__device__ unsigned int g_h1[64 * TOTS];   // bf16x2 pairs, pair-major (coalesced)

// ---- packed f32x2 helpers (FFMA2 via PTX; legal on sm_100 target) ----
#define FFMA2(acc, a, b) \
    asm("fma.rn.f32x2 %0, %1, %2, %0;" : "+l"(acc) : "l"(a), "l"(b))
#define DUPF(dst, fu) \
    asm("mov.b64 %0, {%1, %1};" : "=l"(dst) : "r"(fu))
#define UNPK(lo, hi, v) \
    asm("mov.b64 {%0, %1}, %2;" : "=r"(lo), "=r"(hi) : "l"(v))
#define PACK_BF16X2(out, lo, hi) \
    asm("cvt.rn.bf16x2.f32 %0, %1, %2;" : "=r"(out) : "f"(hi), "f"(lo))

__device__ __forceinline__ float softplus_shift(float v) {
    float x = v - 10.0f;
    return (x > 20.0f) ? x : log1pf(expf(x));
}

struct Tri { int o[8]; float w[8]; };

__device__ __forceinline__ Tri make_tri(float px, float py, float pz) {
    const float k = 2.0f / 3.0f;
    float cx = fminf(fmaxf((px + 1.5f) * k - 1.0f, -1.0f), 1.0f);
    float cy = fminf(fmaxf((py + 1.5f) * k - 1.0f, -1.0f), 1.0f);
    float cz = fminf(fmaxf((pz + 1.5f) * k - 1.0f, -1.0f), 1.0f);
    float fx = (cx + 1.0f) * 63.5f;
    float fy = (cy + 1.0f) * 63.5f;
    float fz = (cz + 1.0f) * 63.5f;
    float x0f = floorf(fx), y0f = floorf(fy), z0f = floorf(fz);
    float wx = fx - x0f, wy = fy - y0f, wz = fz - z0f;
    int ix0 = min(max((int)x0f, 0), 127); int ix1 = min(ix0 + 1, 127);
    int iy0 = min(max((int)y0f, 0), 127); int iy1 = min(iy0 + 1, 127);
    int iz0 = min(max((int)z0f, 0), 127); int iz1 = min(iz0 + 1, 127);
    Tri t;
    int b00 = (iz0 * VOXD + iy0) * VOXD;
    int b01 = (iz0 * VOXD + iy1) * VOXD;
    int b10 = (iz1 * VOXD + iy0) * VOXD;
    int b11 = (iz1 * VOXD + iy1) * VOXD;
    t.o[0] = b00 + ix0; t.o[1] = b00 + ix1;
    t.o[2] = b01 + ix0; t.o[3] = b01 + ix1;
    t.o[4] = b10 + ix0; t.o[5] = b10 + ix1;
    t.o[6] = b11 + ix0; t.o[7] = b11 + ix1;
    float ux = 1.0f - wx, uy = 1.0f - wy, uz = 1.0f - wz;
    t.w[0] = ux * uy * uz; t.w[1] = wx * uy * uz;
    t.w[2] = ux * wy * uz; t.w[3] = wx * wy * uz;
    t.w[4] = ux * uy * wz; t.w[5] = wx * uy * wz;
    t.w[6] = ux * wy * wz; t.w[7] = wx * wy * wz;
    return t;
}

// ---------------- kernel 1: per-sample alpha ----------------
__global__ void sigma_kernel(const float* __restrict__ rays_o,
                             const float* __restrict__ rays_d,
                             const float* __restrict__ dvol, int N) {
    int idx = blockIdx.x * blockDim.x + threadIdx.x;
    if (idx >= N * S_SAMPLES) return;
    int r = idx / S_SAMPLES;
    int s = idx - r * S_SAMPLES;
    float z = 2.0f + (4.0f / 383.0f) * (float)s;
    float px = rays_o[3*r+0] + rays_d[3*r+0] * z;
    float py = rays_o[3*r+1] + rays_d[3*r+1] * z;
    float pz = rays_o[3*r+2] + rays_d[3*r+2] * z;
    bool inb = (px >= -1.5f && px <= 1.5f && py >= -1.5f && py <= 1.5f &&
                pz >= -1.5f && pz <= 1.5f);
    float alpha = 0.0f;
    if (inb && s < S_SAMPLES - 1) {
        Tri t = make_tri(px, py, pz);
        float feat = 0.0f;
        #pragma unroll
        for (int c = 0; c < 8; c++) feat += __ldg(&dvol[t.o[c]]) * t.w[c];
        float sigma = softplus_shift(feat);
        float dist = (2.0f + (4.0f/383.0f)*(float)(s+1)) - z;
        alpha = 1.0f - expf(-sigma * dist * 25.0f);
    }
    g_alpha[idx] = alpha;
}

// ---------------- kernel 2: per-ray transmittance scan ----------------
__global__ void scan_kernel(float* __restrict__ out, int N) {
    int r = blockIdx.x * blockDim.x + threadIdx.x;
    if (r >= N) return;
    float T = 1.0f, acc = 0.0f;
    const int base = r * S_SAMPLES;
    for (int s = 0; s < S_SAMPLES; s++) {
        float a = g_alpha[base + s];
        float w = a * T;
        g_weight[base + s] = w;
        acc += w;
        T *= (1.0f - a + 1e-10f);
    }
    float bg = 1.0f - acc;
    out[3*r+0] = bg; out[3*r+1] = bg; out[3*r+2] = bg;
}

// ---------------- kernel 3a: features + layer 1 -> g_h1 ----------------
// smem: W1 (13056 f) + B1 (128 f) = 13184 floats = 52736 B -> 2 blocks/SM
#define L1_W1   0
#define L1_B1   13056
#define L1_FLOATS 13184
#define L1_BYTES  (L1_FLOATS * 4)

__global__ void __launch_bounds__(256, 2)
l1_kernel(const float* __restrict__ rays_o,
          const float* __restrict__ rays_d,
          const float* __restrict__ avol,
          const float* __restrict__ W1, const float* __restrict__ b1,
          int N, int blk_ofs) {
    extern __shared__ float sm[];
    const int tid = threadIdx.x;
    const int blk = blockIdx.x + blk_ofs;
    const int g = blk * 256 + tid;
    const int r = g / S_SAMPLES;
    const int s = g - r * S_SAMPLES;

    bool active = (g_weight[g] > 0.0f);
    if (!__syncthreads_or(active)) return;

    {
        const float4* g1 = (const float4*)W1;
        float4* s1 = (float4*)&sm[L1_W1];
        for (int i = tid; i < 13056/4; i += 256) s1[i] = g1[i];
        if (tid < 128) sm[L1_B1 + tid] = b1[tid];
    }
    __syncthreads();

    if (active) {
        // ---- features -> xp[51] bf16x2 registers ----
        unsigned int xp[51];
        {
            float z = 2.0f + (4.0f / 383.0f) * (float)s;
            float dx = rays_d[3*r+0], dy = rays_d[3*r+1], dz = rays_d[3*r+2];
            float px = rays_o[3*r+0] + dx * z;
            float py = rays_o[3*r+1] + dy * z;
            float pz = rays_o[3*r+2] + dz * z;

            float feat[30];
            Tri t = make_tri(px, py, pz);
            #pragma unroll
            for (int c = 0; c < CHANS; c++) {
                const float* v = avol + (size_t)c * CH_STRIDE;
                float acc = 0.0f;
                #pragma unroll
                for (int k = 0; k < 8; k++) acc += __ldg(&v[t.o[k]]) * t.w[k];
                feat[c] = acc;
            }
            feat[27] = dx; feat[28] = dy; feat[29] = dz;
            #pragma unroll
            for (int p = 0; p < 15; p++)
                PACK_BF16X2(xp[p], feat[2*p], feat[2*p+1]);
            float p3[3] = {px, py, pz};
            #pragma unroll
            for (int ci = 0; ci < 3; ci++)
                #pragma unroll
                for (int q2 = 0; q2 < 3; q2++) {
                    float a0 = p3[ci] * (float)(1 << (2*q2));
                    float a1 = p3[ci] * (float)(1 << (2*q2+1));
                    float s0, c0, s1, c1;
                    sincosf(a0, &s0, &c0);
                    sincosf(a1, &s1, &c1);
                    PACK_BF16X2(xp[15 + ci*3 + q2], s0, s1);
                    PACK_BF16X2(xp[24 + ci*3 + q2], c0, c1);
                }
            float d3[3] = {dx, dy, dz};
            #pragma unroll
            for (int ci = 0; ci < 3; ci++)
                #pragma unroll
                for (int q2 = 0; q2 < 3; q2++) {
                    float a0 = d3[ci] * (float)(1 << (2*q2));
                    float a1 = d3[ci] * (float)(1 << (2*q2+1));
                    float s0, c0, s1, c1;
                    sincosf(a0, &s0, &c0);
                    sincosf(a1, &s1, &c1);
                    PACK_BF16X2(xp[33 + ci*3 + q2], s0, s1);
                    PACK_BF16X2(xp[42 + ci*3 + q2], c0, c1);
                }
        }

        // ---- layer 1: 8 j-blocks x 16 outputs; kp unrolled (xp in regs) ----
        #pragma unroll 1
        for (int jb = 0; jb < 8; jb++) {
            const int j0 = jb * 16;
            unsigned long long acc[8];
            const unsigned long long* bp =
                (const unsigned long long*)&sm[L1_B1 + j0];
            #pragma unroll
            for (int j = 0; j < 8; j++) acc[j] = bp[j];
            #pragma unroll
            for (int kp = 0; kp < 51; kp++) {
                unsigned int hp = xp[kp];
                unsigned long long xx0, xx1;
                DUPF(xx0, hp << 16);
                DUPF(xx1, hp & 0xffff0000u);
                const ulonglong2* w0 =
                    (const ulonglong2*)&sm[L1_W1 + (2*kp) * 128 + j0];
                const ulonglong2* w1 =
                    (const ulonglong2*)&sm[L1_W1 + (2*kp+1) * 128 + j0];
                #pragma unroll
                for (int j = 0; j < 4; j++) {
                    ulonglong2 ww = w0[j];
                    FFMA2(acc[2*j],   xx0, ww.x);
                    FFMA2(acc[2*j+1], xx0, ww.y);
                }
                #pragma unroll
                for (int j = 0; j < 4; j++) {
                    ulonglong2 ww = w1[j];
                    FFMA2(acc[2*j],   xx1, ww.x);
                    FFMA2(acc[2*j+1], xx1, ww.y);
                }
            }
            // relu + pack + store 8 bf16x2 pairs to g_h1 (pair-major, coalesced)
            #pragma unroll
            for (int j = 0; j < 8; j++) {
                unsigned int lo, hi;
                UNPK(lo, hi, acc[j]);
                float a0 = fmaxf(__uint_as_float(lo), 0.0f);
                float a1 = fmaxf(__uint_as_float(hi), 0.0f);
                unsigned int ph;
                PACK_BF16X2(ph, a0, a1);
                g_h1[(jb*8 + j) * TOTS + g] = ph;
            }
        }
    }
}

// ---------------- kernel 3b: layer 2 + 3 + composite ----------------
// smem: W2 16384 + W3 384 + B2 128 + B3 4 + ACC 8 = 16908 f = 67632 B -> 2 blocks/SM
#define L2_W2   0
#define L2_W3   16384
#define L2_B2   16768
#define L2_B3   16896
#define L2_ACC  16900
#define L2_FLOATS 16908
#define L2_BYTES  (L2_FLOATS * 4)

__global__ void __launch_bounds__(256, 2)
l2_kernel(const float* __restrict__ W2, const float* __restrict__ b2,
          const float* __restrict__ W3, const float* __restrict__ b3,
          float* __restrict__ out, int N, int blk_ofs) {
    extern __shared__ float sm[];
    const int tid = threadIdx.x;
    const int blk = blockIdx.x + blk_ofs;
    const int g = blk * 256 + tid;
    const int r = g / S_SAMPLES;
    const int r0 = (blk * 256) / S_SAMPLES;

    float w = g_weight[g];
    bool active = (w > 0.0f);
    if (!__syncthreads_or(active)) return;

    {
        const float4* g2 = (const float4*)W2;
        float4* s2 = (float4*)&sm[L2_W2];
        for (int i = tid; i < 16384/4; i += 256) s2[i] = g2[i];
        for (int i = tid; i < 384; i += 256) sm[L2_W3 + i] = W3[i];
        if (tid < 128) sm[L2_B2 + tid] = b2[tid];
        if (tid < 3) sm[L2_B3 + tid] = b3[tid];
        if (tid < 8) sm[L2_ACC + tid] = 0.0f;
    }
    __syncthreads();

    if (active) {
        // load own h1 (64 coalesced LDG.32) into true registers
        unsigned int h[64];
        #pragma unroll
        for (int p = 0; p < 64; p++) h[p] = g_h1[p * TOTS + g];

        float o0 = sm[L2_B3 + 0], o1 = sm[L2_B3 + 1], o2 = sm[L2_B3 + 2];
        #pragma unroll 1
        for (int jb = 0; jb < 8; jb++) {
            const int j0 = jb * 16;
            unsigned long long acc[8];
            const unsigned long long* bp =
                (const unsigned long long*)&sm[L2_B2 + j0];
            #pragma unroll
            for (int j = 0; j < 8; j++) acc[j] = bp[j];
            #pragma unroll
            for (int kp = 0; kp < 64; kp++) {
                unsigned int hp = h[kp];
                unsigned long long xx0, xx1;
                DUPF(xx0, hp << 16);
                DUPF(xx1, hp & 0xffff0000u);
                const ulonglong2* w0 =
                    (const ulonglong2*)&sm[L2_W2 + (2*kp) * 128 + j0];
                const ulonglong2* w1 =
                    (const ulonglong2*)&sm[L2_W2 + (2*kp+1) * 128 + j0];
                #pragma unroll
                for (int j = 0; j < 4; j++) {
                    ulonglong2 ww = w0[j];
                    FFMA2(acc[2*j],   xx0, ww.x);
                    FFMA2(acc[2*j+1], xx0, ww.y);
                }
                #pragma unroll
                for (int j = 0; j < 4; j++) {
                    ulonglong2 ww = w1[j];
                    FFMA2(acc[2*j],   xx1, ww.x);
                    FFMA2(acc[2*j+1], xx1, ww.y);
                }
            }
            // relu + fold into layer-3 outputs
            #pragma unroll
            for (int j = 0; j < 8; j++) {
                unsigned int lo, hi;
                UNPK(lo, hi, acc[j]);
                float a0 = fmaxf(__uint_as_float(lo), 0.0f);
                float a1 = fmaxf(__uint_as_float(hi), 0.0f);
                int col = j0 + 2*j;
                o0 = fmaf(a0, sm[L2_W3 + col*3 + 0], o0);
                o1 = fmaf(a0, sm[L2_W3 + col*3 + 1], o1);
                o2 = fmaf(a0, sm[L2_W3 + col*3 + 2], o2);
                o0 = fmaf(a1, sm[L2_W3 + (col+1)*3 + 0], o0);
                o1 = fmaf(a1, sm[L2_W3 + (col+1)*3 + 1], o1);
                o2 = fmaf(a1, sm[L2_W3 + (col+1)*3 + 2], o2);
            }
        }
        float r0v = 1.0f / (1.0f + __expf(-o0));
        float r1v = 1.0f / (1.0f + __expf(-o1));
        float r2v = 1.0f / (1.0f + __expf(-o2));
        int li = r - r0;                       // 0 or 1 (block spans <= 2 rays)
        atomicAdd(&sm[L2_ACC + li*3 + 0], w * r0v);
        atomicAdd(&sm[L2_ACC + li*3 + 1], w * r1v);
        atomicAdd(&sm[L2_ACC + li*3 + 2], w * r2v);
    }
    __syncthreads();
    if (tid < 6) {
        int li = tid / 3, c = tid - li * 3;
        int ray = r0 + li;
        if (ray < N) atomicAdd(&out[3*ray + c], sm[L2_ACC + tid]);
    }
}

// ---------------- kernel 4: clamp ----------------
__global__ void clamp_kernel(float* __restrict__ out, int n) {
    int i = blockIdx.x * blockDim.x + threadIdx.x;
    if (i < n) out[i] = fminf(fmaxf(out[i], 0.0f), 1.0f);
}

extern "C" void kernel_launch(void* const* d_in, const int* in_sizes, int n_in,
                              void* d_out, int out_size) {
    const float* rays_o = (const float*)d_in[0];
    const float* rays_d = (const float*)d_in[1];
    const float* dvol   = (const float*)d_in[2];
    const float* avol   = (const float*)d_in[3];
    const float* W1     = (const float*)d_in[4];
    const float* b1     = (const float*)d_in[5];
    const float* W2     = (const float*)d_in[6];
    const float* b2     = (const float*)d_in[7];
    const float* W3     = (const float*)d_in[8];
    const float* b3     = (const float*)d_in[9];
    float* out = (float*)d_out;
    int N = in_sizes[0] / 3;
    if (N > MAXN) N = MAXN;

    cudaFuncSetAttribute(l1_kernel,
                         cudaFuncAttributeMaxDynamicSharedMemorySize, L1_BYTES);
    cudaFuncSetAttribute(l2_kernel,
                         cudaFuncAttributeMaxDynamicSharedMemorySize, L2_BYTES);

    int total = N * S_SAMPLES;
    sigma_kernel<<<(total + 255) / 256, 256>>>(rays_o, rays_d, dvol, N);
    scan_kernel<<<(N + 255) / 256, 256>>>(out, N);
    int blocks = (total + 255) / 256;
    int half = blocks / 2;
    l1_kernel<<<half, 256, L1_BYTES>>>(rays_o, rays_d, avol, W1, b1, N, 0);
    l1_kernel<<<blocks - half, 256, L1_BYTES>>>(rays_o, rays_d, avol, W1, b1, N, half);
    l2_kernel<<<half, 256, L2_BYTES>>>(W2, b2, W3, b3, out, N, 0);
    l2_kernel<<<blocks - half, 256, L2_BYTES>>>(W2, b2, W3, b3, out, N, half);
    clamp_kernel<<<(N * 3 + 255) / 256, 256>>>(out, N * 3);
}